// round 1
// baseline (speedup 1.0000x reference)
#include <cuda_runtime.h>
#include <cstddef>

typedef unsigned long long u64;

// M matrix, splat layout: for row r (= g*16 + j), column k:
// g_M[(r*32 + k)*2 + 0] = g_M[(r*32 + k)*2 + 1] = U_g[j][k]
// (duplicated so the main kernel can LDS directly into packed f32x2 operands)
__device__ float g_M[4 * 16 * 32 * 2];

// ---------------------------------------------------------------------------
// Precompute kernel: simulate the weight-only circuit on all 32 basis states
// for each of the 4 generators. Thread t = g*32 + k simulates column k of U_g.
// ---------------------------------------------------------------------------
__global__ void precompute_M_kernel(const float* __restrict__ qp)
{
    int t = threadIdx.x;
    if (t >= 128) return;
    int g = t >> 5;
    int k = t & 31;

    float st[32];
#pragma unroll
    for (int i = 0; i < 32; ++i) st[i] = 0.0f;
    st[k] = 1.0f;

#pragma unroll 1
    for (int d = 0; d < 6; ++d) {
        // RY layer
#pragma unroll
        for (int w = 0; w < 5; ++w) {
            float th = qp[g * 30 + d * 5 + w] * 0.5f;
            float s, c;
            sincosf(th, &s, &c);
            const int stride = 16 >> w;
#pragma unroll
            for (int i = 0; i < 32; ++i) {
                if (i & stride) continue;
                float a0 = st[i];
                float a1 = st[i + stride];
                st[i]          = c * a0 - s * a1;
                st[i + stride] = s * a0 + c * a1;
            }
        }
        // CZ layer: flip sign where bits of wires w and w+1 are both 1
#pragma unroll
        for (int w = 0; w < 4; ++w) {
            const int m = (16 >> w) | (8 >> w);
#pragma unroll
            for (int i = 0; i < 32; ++i)
                if ((i & m) == m) st[i] = -st[i];
        }
    }

    // Store rows 0..15 (the only ones the output needs), splatted.
#pragma unroll
    for (int j = 0; j < 16; ++j) {
        int row = g * 16 + j;
        g_M[(row * 32 + k) * 2 + 0] = st[j];
        g_M[(row * 32 + k) * 2 + 1] = st[j];
    }
}

// ---------------------------------------------------------------------------
// Packed f32x2 helpers (Blackwell sm_103a)
// ---------------------------------------------------------------------------
__device__ __forceinline__ u64 pk2(float lo, float hi) {
    u64 r;
    asm("mov.b64 %0, {%1, %2};" : "=l"(r) : "f"(lo), "f"(hi));
    return r;
}
__device__ __forceinline__ void upk2(u64 v, float& lo, float& hi) {
    asm("mov.b64 {%0, %1}, %2;" : "=f"(lo), "=f"(hi) : "l"(v));
}
__device__ __forceinline__ u64 fma2(u64 a, u64 b, u64 c) {
    u64 d;
    asm("fma.rn.f32x2 %0, %1, %2, %3;" : "=l"(d) : "l"(a), "l"(b), "l"(c));
    return d;
}
__device__ __forceinline__ u64 mul2(u64 a, u64 b) {
    u64 d;
    asm("mul.rn.f32x2 %0, %1, %2;" : "=l"(d) : "l"(a), "l"(b));
    return d;
}

// ---------------------------------------------------------------------------
// Main kernel: each thread handles TWO batch elements packed into f32x2 lanes.
// ---------------------------------------------------------------------------
__global__ void __launch_bounds__(128) qsrgan_main_kernel(
    const float* __restrict__ in,
    float* __restrict__ out,
    int npairs, int B)
{
    // 16 KB: M in splat layout [64 rows][32 k][2]
    __shared__ __align__(16) float sM[4 * 16 * 32 * 2];
    {
        const float4* src = (const float4*)g_M;
        float4* dst = (float4*)sM;
#pragma unroll
        for (int i = threadIdx.x; i < 1024; i += 128)
            dst[i] = src[i];
    }
    __syncthreads();

    int pair = blockIdx.x * 128 + threadIdx.x;
    if (pair >= npairs) return;

    size_t b0 = (size_t)pair * 2;
    bool has2 = (b0 + 1 < (size_t)B);

    // noise comes from the first 3 pixels of row 0 of the 4x4 input
    float4 q0 = *(const float4*)(in + b0 * 16);
    float4 q1 = has2 ? *(const float4*)(in + (b0 + 1) * 16) : q0;

    // half-angles: theta_w * 0.5 for the 5 bilinear-upsampled noise values
    float c[5][2], s[5][2];
    {
        float a0 = q0.x, a1 = q0.y, a2 = q0.z;
        float h0 = 0.5f   * a0;
        float h1 = 0.375f * a0 + 0.125f * a1;
        float h2 = 0.125f * a0 + 0.375f * a1;
        float h3 = 0.375f * a1 + 0.125f * a2;
        float h4 = 0.125f * a1 + 0.375f * a2;
        sincosf(h0, &s[0][0], &c[0][0]);
        sincosf(h1, &s[1][0], &c[1][0]);
        sincosf(h2, &s[2][0], &c[2][0]);
        sincosf(h3, &s[3][0], &c[3][0]);
        sincosf(h4, &s[4][0], &c[4][0]);
    }
    {
        float a0 = q1.x, a1 = q1.y, a2 = q1.z;
        float h0 = 0.5f   * a0;
        float h1 = 0.375f * a0 + 0.125f * a1;
        float h2 = 0.125f * a0 + 0.375f * a1;
        float h3 = 0.375f * a1 + 0.125f * a2;
        float h4 = 0.125f * a1 + 0.375f * a2;
        sincosf(h0, &s[0][1], &c[0][1]);
        sincosf(h1, &s[1][1], &c[1][1]);
        sincosf(h2, &s[2][1], &c[2][1]);
        sincosf(h3, &s[3][1], &c[3][1]);
        sincosf(h4, &s[4][1], &c[4][1]);
    }

    u64 cp[5], sp[5];
#pragma unroll
    for (int w = 0; w < 5; ++w) {
        cp[w] = pk2(c[w][0], c[w][1]);
        sp[w] = pk2(s[w][0], s[w][1]);
    }

    // Build the 32-amplitude product state (kron tree), packed over 2 elems.
    // psi index j = b0*16 + b1*8 + b2*4 + b3*2 + b4.
    u64 l1[4], l2[8], l3[16], psi[32];
    l1[0] = mul2(cp[0], cp[1]);
    l1[1] = mul2(cp[0], sp[1]);
    l1[2] = mul2(sp[0], cp[1]);
    l1[3] = mul2(sp[0], sp[1]);
#pragma unroll
    for (int i = 0; i < 4; ++i) {
        l2[2 * i + 0] = mul2(l1[i], cp[2]);
        l2[2 * i + 1] = mul2(l1[i], sp[2]);
    }
#pragma unroll
    for (int i = 0; i < 8; ++i) {
        l3[2 * i + 0] = mul2(l2[i], cp[3]);
        l3[2 * i + 1] = mul2(l2[i], sp[3]);
    }
#pragma unroll
    for (int i = 0; i < 16; ++i) {
        psi[2 * i + 0] = mul2(l3[i], cp[4]);
        psi[2 * i + 1] = mul2(l3[i], sp[4]);
    }

    float* outp0 = out + b0 * 64;
    float* outp1 = out + (b0 + 1) * 64;

#pragma unroll 1
    for (int g = 0; g < 4; ++g) {
        const ulonglong2* Mg = (const ulonglong2*)sM + (size_t)g * 16 * 16;

        u64 acc[16];
#pragma unroll
        for (int j = 0; j < 16; ++j) acc[j] = 0ULL;

#pragma unroll
        for (int j = 0; j < 16; ++j) {
            const ulonglong2* r = Mg + j * 16;
#pragma unroll
            for (int k2 = 0; k2 < 16; ++k2) {
                ulonglong2 mv = r[k2];
                acc[j] = fma2(mv.x, psi[2 * k2 + 0], acc[j]);
                acc[j] = fma2(mv.y, psi[2 * k2 + 1], acc[j]);
            }
        }

        // epilogue: square, max over the 16 outputs, normalize by max
        float p0[16], p1[16];
        float m0 = 0.0f, m1 = 0.0f;
#pragma unroll
        for (int j = 0; j < 16; ++j) {
            float y0, y1;
            upk2(acc[j], y0, y1);
            p0[j] = y0 * y0;
            p1[j] = y1 * y1;
            m0 = fmaxf(m0, p0[j]);
            m1 = fmaxf(m1, p1[j]);
        }
        float r0 = __fdividef(1.0f, m0);
        float r1 = __fdividef(1.0f, m1);

        float4* o0 = (float4*)(outp0 + g * 16);
        o0[0] = make_float4(p0[0] * r0,  p0[1] * r0,  p0[2] * r0,  p0[3] * r0);
        o0[1] = make_float4(p0[4] * r0,  p0[5] * r0,  p0[6] * r0,  p0[7] * r0);
        o0[2] = make_float4(p0[8] * r0,  p0[9] * r0,  p0[10] * r0, p0[11] * r0);
        o0[3] = make_float4(p0[12] * r0, p0[13] * r0, p0[14] * r0, p0[15] * r0);
        if (has2) {
            float4* o1 = (float4*)(outp1 + g * 16);
            o1[0] = make_float4(p1[0] * r1,  p1[1] * r1,  p1[2] * r1,  p1[3] * r1);
            o1[1] = make_float4(p1[4] * r1,  p1[5] * r1,  p1[6] * r1,  p1[7] * r1);
            o1[2] = make_float4(p1[8] * r1,  p1[9] * r1,  p1[10] * r1, p1[11] * r1);
            o1[3] = make_float4(p1[12] * r1, p1[13] * r1, p1[14] * r1, p1[15] * r1);
        }
    }
}

// ---------------------------------------------------------------------------
extern "C" void kernel_launch(void* const* d_in, const int* in_sizes, int n_in,
                              void* d_out, int out_size)
{
    const float* in  = (const float*)d_in[0];   // input: (B,1,4,4) f32
    const float* qp  = (const float*)d_in[1];   // q_params: (4, 30) f32
    float* out = (float*)d_out;                 // (B, 64) f32

    int B = in_sizes[0] / 16;
    int npairs = (B + 1) / 2;
    int blocks = (npairs + 127) / 128;

    precompute_M_kernel<<<1, 128>>>(qp);
    qsrgan_main_kernel<<<blocks, 128>>>(in, out, npairs, B);
}

// round 2
// speedup vs baseline: 1.0670x; 1.0670x over previous
#include <cuda_runtime.h>
#include <cstddef>

typedef unsigned long long u64;

// M matrix, TRANSPOSED splat layout:
//   g_M[((g*32 + k)*16 + j)*2 + {0,1}] = U_g[j][k]   (value duplicated)
// so one k-column of 16 row-values is 32 contiguous floats = 8x LDS.128,
// each LDS.128 yielding two splat f32x2 operands.
__device__ float g_M[4 * 32 * 16 * 2];

// ---------------------------------------------------------------------------
// Precompute: simulate the weight-only circuit on all 32 basis states for
// each of the 4 generators. Thread t = g*32 + k simulates column k of U_g.
// ---------------------------------------------------------------------------
__global__ void precompute_M_kernel(const float* __restrict__ qp)
{
    int t = threadIdx.x;
    if (t >= 128) return;
    int g = t >> 5;
    int k = t & 31;

    float st[32];
#pragma unroll
    for (int i = 0; i < 32; ++i) st[i] = 0.0f;
    st[k] = 1.0f;

#pragma unroll 1
    for (int d = 0; d < 6; ++d) {
#pragma unroll
        for (int w = 0; w < 5; ++w) {
            float th = qp[g * 30 + d * 5 + w] * 0.5f;
            float s, c;
            sincosf(th, &s, &c);
            const int stride = 16 >> w;
#pragma unroll
            for (int i = 0; i < 32; ++i) {
                if (i & stride) continue;
                float a0 = st[i];
                float a1 = st[i + stride];
                st[i]          = c * a0 - s * a1;
                st[i + stride] = s * a0 + c * a1;
            }
        }
#pragma unroll
        for (int w = 0; w < 4; ++w) {
            const int m = (16 >> w) | (8 >> w);
#pragma unroll
            for (int i = 0; i < 32; ++i)
                if ((i & m) == m) st[i] = -st[i];
        }
    }

#pragma unroll
    for (int j = 0; j < 16; ++j) {
        g_M[((g * 32 + k) * 16 + j) * 2 + 0] = st[j];
        g_M[((g * 32 + k) * 16 + j) * 2 + 1] = st[j];
    }
}

// ---------------------------------------------------------------------------
// Packed f32x2 helpers (Blackwell sm_103a)
// ---------------------------------------------------------------------------
__device__ __forceinline__ u64 pk2(float lo, float hi) {
    u64 r;
    asm("mov.b64 %0, {%1, %2};" : "=l"(r) : "f"(lo), "f"(hi));
    return r;
}
__device__ __forceinline__ void upk2(u64 v, float& lo, float& hi) {
    asm("mov.b64 {%0, %1}, %2;" : "=f"(lo), "=f"(hi) : "l"(v));
}
__device__ __forceinline__ u64 fma2(u64 a, u64 b, u64 c) {
    u64 d;
    asm("fma.rn.f32x2 %0, %1, %2, %3;" : "=l"(d) : "l"(a), "l"(b), "l"(c));
    return d;
}
__device__ __forceinline__ u64 mul2(u64 a, u64 b) {
    u64 d;
    asm("mul.rn.f32x2 %0, %1, %2;" : "=l"(d) : "l"(a), "l"(b));
    return d;
}

// Build Kronecker factors for one f32x2 pair of batch elements from the two
// float4 loads (first 3 pixels of row 0 of each 4x4 image).
__device__ __forceinline__ void build_psi_factors(
    float4 qa, float4 qb, u64 pa[8], u64 pb[4])
{
    float c[5][2], s[5][2];
#pragma unroll
    for (int e = 0; e < 2; ++e) {
        float a0 = e ? qb.x : qa.x;
        float a1 = e ? qb.y : qa.y;
        float a2 = e ? qb.z : qa.z;
        float h0 = 0.5f   * a0;
        float h1 = 0.375f * a0 + 0.125f * a1;
        float h2 = 0.125f * a0 + 0.375f * a1;
        float h3 = 0.375f * a1 + 0.125f * a2;
        float h4 = 0.125f * a1 + 0.375f * a2;
        __sincosf(h0, &s[0][e], &c[0][e]);
        __sincosf(h1, &s[1][e], &c[1][e]);
        __sincosf(h2, &s[2][e], &c[2][e]);
        __sincosf(h3, &s[3][e], &c[3][e]);
        __sincosf(h4, &s[4][e], &c[4][e]);
    }
    u64 cp[5], sp[5];
#pragma unroll
    for (int w = 0; w < 5; ++w) {
        cp[w] = pk2(c[w][0], c[w][1]);
        sp[w] = pk2(s[w][0], s[w][1]);
    }
    // pa[ka], ka = b0b1b2 (wire0 = MSB of 3-bit index)
    u64 t01[4];
    t01[0] = mul2(cp[0], cp[1]);
    t01[1] = mul2(cp[0], sp[1]);
    t01[2] = mul2(sp[0], cp[1]);
    t01[3] = mul2(sp[0], sp[1]);
#pragma unroll
    for (int i = 0; i < 4; ++i) {
        pa[2 * i + 0] = mul2(t01[i], cp[2]);
        pa[2 * i + 1] = mul2(t01[i], sp[2]);
    }
    // pb[kb], kb = b3b4
    pb[0] = mul2(cp[3], cp[4]);
    pb[1] = mul2(cp[3], sp[4]);
    pb[2] = mul2(sp[3], cp[4]);
    pb[3] = mul2(sp[3], sp[4]);
}

// ---------------------------------------------------------------------------
// Main kernel: each thread handles FOUR batch elements (2 f32x2 pairs).
// Column-major matvec so each LDS.128 of splat-M feeds 4 FFMA2.
// ---------------------------------------------------------------------------
__global__ void __launch_bounds__(128) qsrgan_main_kernel(
    const float* __restrict__ in,
    float* __restrict__ out,
    int B)
{
    __shared__ __align__(16) float sM[4 * 32 * 16 * 2];  // 16 KB
    {
        const float4* src = (const float4*)g_M;
        float4* dst = (float4*)sM;
#pragma unroll
        for (int i = threadIdx.x; i < 1024; i += 128)
            dst[i] = src[i];
    }
    __syncthreads();

    long long b = ((long long)blockIdx.x * 128 + threadIdx.x) * 4;
    if (b >= B) return;
    long long i1 = (b + 1 < B) ? b + 1 : b;
    long long i2 = (b + 2 < B) ? b + 2 : b;
    long long i3 = (b + 3 < B) ? b + 3 : b;

    float4 q0 = *(const float4*)(in + b  * 16);
    float4 q1 = *(const float4*)(in + i1 * 16);
    float4 q2 = *(const float4*)(in + i2 * 16);
    float4 q3 = *(const float4*)(in + i3 * 16);

    u64 pa0[8], pb0[4], pa1[8], pb1[4];
    build_psi_factors(q0, q1, pa0, pb0);
    build_psi_factors(q2, q3, pa1, pb1);

#pragma unroll 1
    for (int g = 0; g < 4; ++g) {
        const ulonglong2* Mg = (const ulonglong2*)sM + g * 32 * 8;

        u64 acc0[16], acc1[16];
#pragma unroll
        for (int j = 0; j < 16; ++j) { acc0[j] = 0ULL; acc1[j] = 0ULL; }

#pragma unroll
        for (int ka = 0; ka < 8; ++ka) {
#pragma unroll
            for (int kb = 0; kb < 4; ++kb) {
                const int k = ka * 4 + kb;
                u64 pk0 = mul2(pa0[ka], pb0[kb]);
                u64 pk1 = mul2(pa1[ka], pb1[kb]);
                const ulonglong2* col = Mg + k * 8;
#pragma unroll
                for (int j2 = 0; j2 < 8; ++j2) {
                    ulonglong2 mv = col[j2];
                    acc0[2 * j2 + 0] = fma2(mv.x, pk0, acc0[2 * j2 + 0]);
                    acc0[2 * j2 + 1] = fma2(mv.y, pk0, acc0[2 * j2 + 1]);
                    acc1[2 * j2 + 0] = fma2(mv.x, pk1, acc1[2 * j2 + 0]);
                    acc1[2 * j2 + 1] = fma2(mv.y, pk1, acc1[2 * j2 + 1]);
                }
            }
        }

        // epilogue: square, per-element max over 16 outputs, scale, store
        float pA[16], pB[16], pC[16], pD[16];
        float mA = 0.0f, mB = 0.0f, mC = 0.0f, mD = 0.0f;
#pragma unroll
        for (int j = 0; j < 16; ++j) {
            float yA, yB, yC, yD;
            upk2(acc0[j], yA, yB);
            upk2(acc1[j], yC, yD);
            pA[j] = yA * yA; mA = fmaxf(mA, pA[j]);
            pB[j] = yB * yB; mB = fmaxf(mB, pB[j]);
            pC[j] = yC * yC; mC = fmaxf(mC, pC[j]);
            pD[j] = yD * yD; mD = fmaxf(mD, pD[j]);
        }
        float rA = __fdividef(1.0f, mA);
        float rB = __fdividef(1.0f, mB);
        float rC = __fdividef(1.0f, mC);
        float rD = __fdividef(1.0f, mD);

        {
            float4* o = (float4*)(out + b * 64 + g * 16);
            o[0] = make_float4(pA[0]*rA,  pA[1]*rA,  pA[2]*rA,  pA[3]*rA);
            o[1] = make_float4(pA[4]*rA,  pA[5]*rA,  pA[6]*rA,  pA[7]*rA);
            o[2] = make_float4(pA[8]*rA,  pA[9]*rA,  pA[10]*rA, pA[11]*rA);
            o[3] = make_float4(pA[12]*rA, pA[13]*rA, pA[14]*rA, pA[15]*rA);
        }
        if (b + 1 < B) {
            float4* o = (float4*)(out + i1 * 64 + g * 16);
            o[0] = make_float4(pB[0]*rB,  pB[1]*rB,  pB[2]*rB,  pB[3]*rB);
            o[1] = make_float4(pB[4]*rB,  pB[5]*rB,  pB[6]*rB,  pB[7]*rB);
            o[2] = make_float4(pB[8]*rB,  pB[9]*rB,  pB[10]*rB, pB[11]*rB);
            o[3] = make_float4(pB[12]*rB, pB[13]*rB, pB[14]*rB, pB[15]*rB);
        }
        if (b + 2 < B) {
            float4* o = (float4*)(out + i2 * 64 + g * 16);
            o[0] = make_float4(pC[0]*rC,  pC[1]*rC,  pC[2]*rC,  pC[3]*rC);
            o[1] = make_float4(pC[4]*rC,  pC[5]*rC,  pC[6]*rC,  pC[7]*rC);
            o[2] = make_float4(pC[8]*rC,  pC[9]*rC,  pC[10]*rC, pC[11]*rC);
            o[3] = make_float4(pC[12]*rC, pC[13]*rC, pC[14]*rC, pC[15]*rC);
        }
        if (b + 3 < B) {
            float4* o = (float4*)(out + i3 * 64 + g * 16);
            o[0] = make_float4(pD[0]*rD,  pD[1]*rD,  pD[2]*rD,  pD[3]*rD);
            o[1] = make_float4(pD[4]*rD,  pD[5]*rD,  pD[6]*rD,  pD[7]*rD);
            o[2] = make_float4(pD[8]*rD,  pD[9]*rD,  pD[10]*rD, pD[11]*rD);
            o[3] = make_float4(pD[12]*rD, pD[13]*rD, pD[14]*rD, pD[15]*rD);
        }
    }
}

// ---------------------------------------------------------------------------
extern "C" void kernel_launch(void* const* d_in, const int* in_sizes, int n_in,
                              void* d_out, int out_size)
{
    const float* in = (const float*)d_in[0];   // (B,1,4,4) f32
    const float* qp = (const float*)d_in[1];   // (4, 30) f32
    float* out = (float*)d_out;                // (B, 64) f32

    int B = in_sizes[0] / 16;
    int nthreads = (B + 3) / 4;
    int blocks = (nthreads + 127) / 128;

    precompute_M_kernel<<<1, 128>>>(qp);
    qsrgan_main_kernel<<<blocks, 128>>>(in, out, B);
}